// round 1
// baseline (speedup 1.0000x reference)
#include <cuda_runtime.h>
#include <cuda_bf16.h>
#include <math.h>

// Problem constants
#define BB   4
#define LSEQ 4096
#define HD   1024
#define UD   1024
#define U3   3072
#define NCHUNK 64
#define LC     64   // NCHUNK * LC == LSEQ

// Scratch (allocation-free: __device__ globals)
__device__ float g_rkv[(size_t)BB * LSEQ * U3];      // 192 MB: raw rkv, then (r_raw, exp(k), exp(k)*v)
__device__ float g_x[(size_t)BB * LSEQ * UD];        // 64 MB
__device__ float g_part[(size_t)BB * NCHUNK * 2 * UD]; // 2 MB: chunk partials / prefixes

// ---------------------------------------------------------------------------
// Classic fp32 SGEMM: 128x128 tile, BK=16, 256 threads, 8x8 per thread,
// double-buffered shared memory. C = A[MxK] * B[KxN] + bias[N].
// M % 128 == 0, N % 128 == 0, K % 16 == 0 (all hold here).
// ---------------------------------------------------------------------------
__global__ void __launch_bounds__(256) sgemm128(
    const float* __restrict__ A, const float* __restrict__ Bm,
    const float* __restrict__ bias, float* __restrict__ C,
    int M, int N, int K)
{
    __shared__ float As[2][16][128];
    __shared__ float Bs[2][16][128];

    const int tid = threadIdx.x;
    const int m0 = blockIdx.y * 128;
    const int n0 = blockIdx.x * 128;

    // A-tile loader mapping: 512 float4 per tile, 2 per thread
    const int am = tid >> 2;            // 0..63 (second load at am+64)
    const int ak = (tid & 3) << 2;      // 0,4,8,12
    // B-tile loader mapping
    const int bk = tid >> 5;            // 0..7 (second load at bk+8)
    const int bn = (tid & 31) << 2;     // 0..124 step 4

    const float* Ap = A + (size_t)m0 * K;
    const float* Bp = Bm + n0;

    const int tm = (tid >> 4) << 3;     // 0..120 step 8
    const int tn = (tid & 15) << 3;     // 0..120 step 8

    float acc[8][8];
    #pragma unroll
    for (int i = 0; i < 8; i++)
        #pragma unroll
        for (int j = 0; j < 8; j++)
            acc[i][j] = 0.f;

    // Prologue: load k-tile 0
    {
        float4 a0 = *(const float4*)(Ap + (size_t)am * K + ak);
        float4 a1 = *(const float4*)(Ap + (size_t)(am + 64) * K + ak);
        float4 b0 = *(const float4*)(Bp + (size_t)bk * N + bn);
        float4 b1 = *(const float4*)(Bp + (size_t)(bk + 8) * N + bn);
        As[0][ak + 0][am] = a0.x; As[0][ak + 1][am] = a0.y;
        As[0][ak + 2][am] = a0.z; As[0][ak + 3][am] = a0.w;
        As[0][ak + 0][am + 64] = a1.x; As[0][ak + 1][am + 64] = a1.y;
        As[0][ak + 2][am + 64] = a1.z; As[0][ak + 3][am + 64] = a1.w;
        *(float4*)&Bs[0][bk][bn]     = b0;
        *(float4*)&Bs[0][bk + 8][bn] = b1;
    }
    __syncthreads();

    const int NT = K >> 4;
    int s = 0;
    for (int kt = 0; kt < NT; ++kt) {
        float4 na0, na1, nb0, nb1;
        const bool more = (kt + 1 < NT);
        if (more) {
            const int kg = (kt + 1) << 4;
            na0 = *(const float4*)(Ap + (size_t)am * K + kg + ak);
            na1 = *(const float4*)(Ap + (size_t)(am + 64) * K + kg + ak);
            nb0 = *(const float4*)(Bp + (size_t)(kg + bk) * N + bn);
            nb1 = *(const float4*)(Bp + (size_t)(kg + bk + 8) * N + bn);
        }
        #pragma unroll
        for (int k = 0; k < 16; k++) {
            float ar[8], br[8];
            *(float4*)&ar[0] = *(const float4*)&As[s][k][tm];
            *(float4*)&ar[4] = *(const float4*)&As[s][k][tm + 4];
            *(float4*)&br[0] = *(const float4*)&Bs[s][k][tn];
            *(float4*)&br[4] = *(const float4*)&Bs[s][k][tn + 4];
            #pragma unroll
            for (int i = 0; i < 8; i++)
                #pragma unroll
                for (int j = 0; j < 8; j++)
                    acc[i][j] = fmaf(ar[i], br[j], acc[i][j]);
        }
        if (more) {
            const int t = s ^ 1;
            As[t][ak + 0][am] = na0.x; As[t][ak + 1][am] = na0.y;
            As[t][ak + 2][am] = na0.z; As[t][ak + 3][am] = na0.w;
            As[t][ak + 0][am + 64] = na1.x; As[t][ak + 1][am + 64] = na1.y;
            As[t][ak + 2][am + 64] = na1.z; As[t][ak + 3][am + 64] = na1.w;
            *(float4*)&Bs[t][bk][bn]     = nb0;
            *(float4*)&Bs[t][bk + 8][bn] = nb1;
            __syncthreads();
            s = t;
        }
    }

    // Epilogue: add bias, vectorized store
    float4 bi0 = *(const float4*)(bias + n0 + tn);
    float4 bi1 = *(const float4*)(bias + n0 + tn + 4);
    #pragma unroll
    for (int i = 0; i < 8; i++) {
        float4 o0, o1;
        o0.x = acc[i][0] + bi0.x; o0.y = acc[i][1] + bi0.y;
        o0.z = acc[i][2] + bi0.z; o0.w = acc[i][3] + bi0.w;
        o1.x = acc[i][4] + bi1.x; o1.y = acc[i][5] + bi1.y;
        o1.z = acc[i][6] + bi1.z; o1.w = acc[i][7] + bi1.w;
        float* crow = C + (size_t)(m0 + tm + i) * N + n0 + tn;
        *(float4*)(crow)     = o0;
        *(float4*)(crow + 4) = o1;
    }
}

// ---------------------------------------------------------------------------
// Chunked linear-recurrence scan: y_t = lam*y_{t-1} + u_t, per (batch, channel).
// Phase A: per-chunk local scan ending values; also caches exp(k), exp(k)*v
//          in-place (so exp is computed once per element).
// Phase B: serial prefix across NCHUNK chunks (tiny).
// Phase C: re-scan with prefix, compute x and store.
// ---------------------------------------------------------------------------
__global__ void __launch_bounds__(256) scan_phaseA(const float* __restrict__ nu_log)
{
    const int c = blockIdx.x * blockDim.x + threadIdx.x;  // channel 0..UD-1
    const int chunk = blockIdx.y;
    const int b = blockIdx.z;
    const float lam = expf(-expf(nu_log[c]));

    size_t base = ((size_t)b * LSEQ + (size_t)chunk * LC) * U3;
    float y1 = 0.f, y2 = 0.f;
    #pragma unroll 4
    for (int i = 0; i < LC; i++) {
        size_t off = base + (size_t)i * U3;
        float kr = g_rkv[off + UD + c];
        float vr = g_rkv[off + 2 * UD + c];
        float kk = expf(kr);
        float kv = kk * vr;
        g_rkv[off + UD + c]     = kk;   // cache exp(k)
        g_rkv[off + 2 * UD + c] = kv;   // cache exp(k)*v
        y1 = fmaf(y1, lam, kv);
        y2 = fmaf(y2, lam, kk);
    }
    size_t p = (size_t)(b * NCHUNK + chunk) * 2 * UD + c;
    g_part[p]      = y1;
    g_part[p + UD] = y2;
}

__global__ void __launch_bounds__(256) scan_phaseB(const float* __restrict__ nu_log)
{
    const int c = blockIdx.x * blockDim.x + threadIdx.x;
    const int b = blockIdx.y;
    const float lam = expf(-expf(nu_log[c]));
    const float lamLc = powf(lam, (float)LC);
    float Y1 = 0.f, Y2 = 0.f;
    for (int j = 0; j < NCHUNK; j++) {
        size_t p = (size_t)(b * NCHUNK + j) * 2 * UD + c;
        float S1 = g_part[p], S2 = g_part[p + UD];
        g_part[p]      = Y1;   // value entering chunk j
        g_part[p + UD] = Y2;
        Y1 = fmaf(Y1, lamLc, S1);
        Y2 = fmaf(Y2, lamLc, S2);
    }
}

__global__ void __launch_bounds__(256) scan_phaseC(const float* __restrict__ nu_log,
                                                   const float* __restrict__ gamma_log)
{
    const int c = blockIdx.x * blockDim.x + threadIdx.x;
    const int chunk = blockIdx.y;
    const int b = blockIdx.z;
    const float lam = expf(-expf(nu_log[c]));
    const float gamma = expf(nu_log[c] + gamma_log[c]) - 1.f;

    size_t p = (size_t)(b * NCHUNK + chunk) * 2 * UD + c;
    float y1 = g_part[p];
    float y2 = g_part[p + UD];

    size_t base  = ((size_t)b * LSEQ + (size_t)chunk * LC) * U3;
    size_t xbase = ((size_t)b * LSEQ + (size_t)chunk * LC) * UD;
    #pragma unroll 4
    for (int i = 0; i < LC; i++) {
        size_t off = base + (size_t)i * U3;
        float rr = g_rkv[off + c];            // raw r
        float kk = g_rkv[off + UD + c];       // exp(k), cached
        float kv = g_rkv[off + 2 * UD + c];   // exp(k)*v, cached
        y1 = fmaf(y1, lam, kv);
        y2 = fmaf(y2, lam, kk);
        float r = 1.f / (1.f + expf(-rr));
        float x = (y1 + gamma * kv) / (y2 + gamma * kk + 1e-6f) * r;
        g_x[xbase + (size_t)i * UD + c] = x;
    }
}

// ---------------------------------------------------------------------------
// Launch
// ---------------------------------------------------------------------------
extern "C" void kernel_launch(void* const* d_in, const int* in_sizes, int n_in,
                              void* d_out, int out_size)
{
    const float* inputs    = (const float*)d_in[0];  // [B,L,H]
    const float* W_rkv     = (const float*)d_in[1];  // [H,3U]
    const float* b_rkv     = (const float*)d_in[2];  // [3U]
    const float* W_o       = (const float*)d_in[3];  // [U,H]
    const float* b_o       = (const float*)d_in[4];  // [H]
    const float* nu_log    = (const float*)d_in[5];  // [U]
    const float* gamma_log = (const float*)d_in[6];  // [U]
    float* out = (float*)d_out;

    float *p_rkv = nullptr, *p_x = nullptr;
    cudaGetSymbolAddress((void**)&p_rkv, g_rkv);
    cudaGetSymbolAddress((void**)&p_x, g_x);

    const int M = BB * LSEQ;  // 16384
    dim3 blk(256);

    // GEMM1: rkv = inputs @ W_rkv + b_rkv   [16384, 3072]
    sgemm128<<<dim3(U3 / 128, M / 128), blk>>>(inputs, W_rkv, b_rkv, p_rkv, M, U3, HD);

    // Scan (3 phases)
    scan_phaseA<<<dim3(UD / 256, NCHUNK, BB), blk>>>(nu_log);
    scan_phaseB<<<dim3(UD / 256, BB), blk>>>(nu_log);
    scan_phaseC<<<dim3(UD / 256, NCHUNK, BB), blk>>>(nu_log, gamma_log);

    // GEMM2: out = x @ W_o + b_o   [16384, 1024]
    sgemm128<<<dim3(HD / 128, M / 128), blk>>>(p_x, W_o, b_o, out, M, HD, UD);
}

// round 4
// speedup vs baseline: 1.8198x; 1.8198x over previous
#include <cuda_runtime.h>
#include <cuda_bf16.h>
#include <math.h>
#include <stdint.h>

// Problem constants
#define BB   4
#define LSEQ 4096
#define HD   1024
#define UD   1024
#define U3   3072
#define NCHUNK 64
#define LC     64
#define K2   2048           // stored split K: [hi | lo]
#define MROWS (BB*LSEQ)     // 16384

// Scratch (allocation-free: __device__ globals)
__device__ float g_rkv[(size_t)BB * LSEQ * U3];        // 192 MB fp32
__device__ float g_x[(size_t)BB * LSEQ * UD];          // 64 MB
__device__ float g_part[(size_t)BB * NCHUNK * 2 * UD]; // 2 MB
__device__ __nv_bfloat16 g_Ah[(size_t)MROWS * K2];     // 64 MB: split(inputs)
__device__ __nv_bfloat16 g_Xh[(size_t)MROWS * K2];     // 64 MB: split(x)
__device__ __nv_bfloat16 g_B1[(size_t)U3 * K2];        // 12 MB: split+T(W_rkv)
__device__ __nv_bfloat16 g_B2[(size_t)HD * K2];        //  4 MB: split+T(W_o)

__device__ __forceinline__ void cpa16(void* s, const void* g) {
    uint32_t sa = (uint32_t)__cvta_generic_to_shared(s);
    asm volatile("cp.async.cg.shared.global [%0], [%1], 16;" :: "r"(sa), "l"(g));
}

// ---------------------------------------------------------------------------
// bf16 warp-MMA GEMM (mma.sync m16n8k16, fp32 accum) with 3-term hi/lo split:
//   C = A_hi*B_hi + A_hi*B_lo + A_lo*B_hi  (~fp32 accuracy; A_lo*B_lo ~2^-18 dropped)
// Operands stored [row, 2048] = [hi(1024) | lo(1024)], K-contiguous.
// 96 virtual K-chunks of 32: seg 0: (Ahi,Bhi), seg 1: (Ahi,Blo), seg 2: (Alo,Bhi).
// CTA tile 128x128, 256 threads (8 warps 2x4), double-buffered cp.async.
// SMEM rows padded to 40 bf16 -> conflict-free fragment loads.
// ---------------------------------------------------------------------------
__global__ void __launch_bounds__(256) gemm_mma(
    const __nv_bfloat16* __restrict__ A,
    const __nv_bfloat16* __restrict__ Bt,
    const float* __restrict__ bias,
    float* __restrict__ C, int N)
{
    __shared__ __nv_bfloat16 As[2][128][40];
    __shared__ __nv_bfloat16 Bs[2][128][40];

    const int tid  = threadIdx.x;
    const int m0   = blockIdx.y * 128;
    const int n0   = blockIdx.x * 128;
    const int warp = tid >> 5;
    const int lane = tid & 31;
    const int wm   = (warp >> 2) * 64;   // 0 or 64
    const int wn   = (warp & 3) * 32;    // 0,32,64,96
    const int gm   = lane >> 2;          // 0..7
    const int kq   = (lane & 3) * 2;     // 0,2,4,6

    float acc[4][4][4];
    #pragma unroll
    for (int i = 0; i < 4; i++)
        #pragma unroll
        for (int j = 0; j < 4; j++)
            #pragma unroll
            for (int t = 0; t < 4; t++)
                acc[i][j][t] = 0.f;

    // loader: virtual chunk ci (0..95) -> buffer b
    const int lr = tid >> 2;        // 0..63 base row
    const int lj = (tid & 3) * 8;   // 16B segment within 64B row-chunk
    auto load_chunk = [&](int ci, int b) {
        const int s   = ci >> 5;            // segment 0,1,2
        const int kof = (ci & 31) << 5;     // 0..992
        const size_t kA = (size_t)((s == 2) ? 1024 : 0) + kof;   // A: hi,hi,lo
        const size_t kB = (size_t)((s == 1) ? 1024 : 0) + kof;   // B: hi,lo,hi
        #pragma unroll
        for (int h = 0; h < 2; h++) {
            int r = lr + h * 64;
            cpa16(&As[b][r][lj], A  + (size_t)(m0 + r) * K2 + kA + lj);
            cpa16(&Bs[b][r][lj], Bt + (size_t)(n0 + r) * K2 + kB + lj);
        }
        asm volatile("cp.async.commit_group;");
    };

    load_chunk(0, 0);

    const int NCH = 96;   // 3 segments x 32 chunks
    for (int ci = 0; ci < NCH; ci++) {
        const int b = ci & 1;
        if (ci + 1 < NCH) {
            load_chunk(ci + 1, b ^ 1);
            asm volatile("cp.async.wait_group 1;" ::: "memory");
        } else {
            asm volatile("cp.async.wait_group 0;" ::: "memory");
        }
        __syncthreads();

        #pragma unroll
        for (int kk = 0; kk < 2; kk++) {      // two k16 halves of the 32-chunk
            const int kc = kk * 16 + kq;
            uint32_t af[4][4], bf[4][2];
            #pragma unroll
            for (int i = 0; i < 4; i++) {
                int r = wm + i * 16 + gm;
                af[i][0] = *(const uint32_t*)&As[b][r][kc];
                af[i][1] = *(const uint32_t*)&As[b][r + 8][kc];
                af[i][2] = *(const uint32_t*)&As[b][r][kc + 8];
                af[i][3] = *(const uint32_t*)&As[b][r + 8][kc + 8];
            }
            #pragma unroll
            for (int j = 0; j < 4; j++) {
                int n = wn + j * 8 + gm;
                bf[j][0] = *(const uint32_t*)&Bs[b][n][kc];
                bf[j][1] = *(const uint32_t*)&Bs[b][n][kc + 8];
            }
            #pragma unroll
            for (int i = 0; i < 4; i++)
                #pragma unroll
                for (int j = 0; j < 4; j++)
                    asm volatile(
                        "mma.sync.aligned.m16n8k16.row.col.f32.bf16.bf16.f32 "
                        "{%0,%1,%2,%3}, {%4,%5,%6,%7}, {%8,%9}, {%0,%1,%2,%3};"
                        : "+f"(acc[i][j][0]), "+f"(acc[i][j][1]),
                          "+f"(acc[i][j][2]), "+f"(acc[i][j][3])
                        : "r"(af[i][0]), "r"(af[i][1]), "r"(af[i][2]), "r"(af[i][3]),
                          "r"(bf[j][0]), "r"(bf[j][1]));
        }
        __syncthreads();
    }

    // Epilogue: bias + store (float2 per fragment row)
    #pragma unroll
    for (int j = 0; j < 4; j++) {
        const int col = n0 + wn + j * 8 + kq;
        const float b0 = bias[col], b1 = bias[col + 1];
        #pragma unroll
        for (int i = 0; i < 4; i++) {
            const int row = m0 + wm + i * 16 + gm;
            float2 v0 = make_float2(acc[i][j][0] + b0, acc[i][j][1] + b1);
            float2 v1 = make_float2(acc[i][j][2] + b0, acc[i][j][3] + b1);
            *(float2*)&C[(size_t)row * N + col]       = v0;
            *(float2*)&C[(size_t)(row + 8) * N + col] = v1;
        }
    }
}

// ---------------------------------------------------------------------------
// fp32 -> bf16 hi/lo split, row layout [R,1024] -> [R,2048] ([hi|lo])
// ---------------------------------------------------------------------------
__global__ void __launch_bounds__(256) split_rows(const float* __restrict__ X,
                                                  __nv_bfloat16* __restrict__ Y, int total4)
{
    int idx = blockIdx.x * 256 + threadIdx.x;
    if (idx >= total4) return;
    int r = idx >> 8;          // 256 float4 per row (K=1024)
    int c4 = idx & 255;
    float4 v = ((const float4*)X)[idx];
    float f[4] = { v.x, v.y, v.z, v.w };
    ushort4 hv, lv;
    unsigned short* hp = &hv.x; unsigned short* lp = &lv.x;
    #pragma unroll
    for (int i = 0; i < 4; i++) {
        __nv_bfloat16 h = __float2bfloat16(f[i]);
        __nv_bfloat16 l = __float2bfloat16(f[i] - __bfloat162float(h));
        hp[i] = __bfloat16_as_ushort(h);
        lp[i] = __bfloat16_as_ushort(l);
    }
    size_t o = (size_t)r * K2 + (c4 << 2);
    *(ushort4*)((unsigned short*)Y + o)         = hv;
    *(ushort4*)((unsigned short*)Y + o + 1024)  = lv;
}

// ---------------------------------------------------------------------------
// W[K,N] fp32 -> Bt[N,2048] bf16 (transpose + split), tiled 32x32
// ---------------------------------------------------------------------------
__global__ void split_T(const float* __restrict__ W, __nv_bfloat16* __restrict__ Bt,
                        int Kdim, int Ncols)
{
    __shared__ float t[32][33];
    int n = blockIdx.x * 32 + threadIdx.x;
    int k0 = blockIdx.y * 32;
    for (int i = threadIdx.y; i < 32; i += 8)
        t[i][threadIdx.x] = W[(size_t)(k0 + i) * Ncols + n];
    __syncthreads();
    int k = k0 + threadIdx.x;
    for (int i = threadIdx.y; i < 32; i += 8) {
        int nn = blockIdx.x * 32 + i;
        float v = t[threadIdx.x][i];
        __nv_bfloat16 h = __float2bfloat16(v);
        __nv_bfloat16 l = __float2bfloat16(v - __bfloat162float(h));
        Bt[(size_t)nn * K2 + k]        = h;
        Bt[(size_t)nn * K2 + 1024 + k] = l;
    }
}

// ---------------------------------------------------------------------------
// Chunked linear-recurrence scan (3 phases)
// ---------------------------------------------------------------------------
__global__ void __launch_bounds__(256) scan_phaseA(const float* __restrict__ nu_log)
{
    const int c = blockIdx.x * blockDim.x + threadIdx.x;
    const int chunk = blockIdx.y;
    const int b = blockIdx.z;
    const float lam = expf(-expf(nu_log[c]));

    size_t base = ((size_t)b * LSEQ + (size_t)chunk * LC) * U3;
    float y1 = 0.f, y2 = 0.f;
    #pragma unroll 4
    for (int i = 0; i < LC; i++) {
        size_t off = base + (size_t)i * U3;
        float kr = g_rkv[off + UD + c];
        float vr = g_rkv[off + 2 * UD + c];
        float kk = expf(kr);
        float kv = kk * vr;
        g_rkv[off + UD + c]     = kk;
        g_rkv[off + 2 * UD + c] = kv;
        y1 = fmaf(y1, lam, kv);
        y2 = fmaf(y2, lam, kk);
    }
    size_t p = (size_t)(b * NCHUNK + chunk) * 2 * UD + c;
    g_part[p]      = y1;
    g_part[p + UD] = y2;
}

__global__ void __launch_bounds__(256) scan_phaseB(const float* __restrict__ nu_log)
{
    const int c = blockIdx.x * blockDim.x + threadIdx.x;
    const int b = blockIdx.y;
    const float lam = expf(-expf(nu_log[c]));
    const float lamLc = powf(lam, (float)LC);
    float Y1 = 0.f, Y2 = 0.f;
    for (int j = 0; j < NCHUNK; j++) {
        size_t p = (size_t)(b * NCHUNK + j) * 2 * UD + c;
        float S1 = g_part[p], S2 = g_part[p + UD];
        g_part[p]      = Y1;
        g_part[p + UD] = Y2;
        Y1 = fmaf(Y1, lamLc, S1);
        Y2 = fmaf(Y2, lamLc, S2);
    }
}

__global__ void __launch_bounds__(256) scan_phaseC(const float* __restrict__ nu_log,
                                                   const float* __restrict__ gamma_log)
{
    const int c = blockIdx.x * blockDim.x + threadIdx.x;
    const int chunk = blockIdx.y;
    const int b = blockIdx.z;
    const float lam = expf(-expf(nu_log[c]));
    const float gamma = expf(nu_log[c] + gamma_log[c]) - 1.f;

    size_t p = (size_t)(b * NCHUNK + chunk) * 2 * UD + c;
    float y1 = g_part[p];
    float y2 = g_part[p + UD];

    size_t base  = ((size_t)b * LSEQ + (size_t)chunk * LC) * U3;
    size_t xbase = ((size_t)b * LSEQ + (size_t)chunk * LC) * UD;
    #pragma unroll 4
    for (int i = 0; i < LC; i++) {
        size_t off = base + (size_t)i * U3;
        float rr = g_rkv[off + c];
        float kk = g_rkv[off + UD + c];
        float kv = g_rkv[off + 2 * UD + c];
        y1 = fmaf(y1, lam, kv);
        y2 = fmaf(y2, lam, kk);
        float r = 1.f / (1.f + expf(-rr));
        float x = (y1 + gamma * kv) / (y2 + gamma * kk + 1e-6f) * r;
        g_x[xbase + (size_t)i * UD + c] = x;
    }
}

// ---------------------------------------------------------------------------
// Launch
// ---------------------------------------------------------------------------
extern "C" void kernel_launch(void* const* d_in, const int* in_sizes, int n_in,
                              void* d_out, int out_size)
{
    const float* inputs    = (const float*)d_in[0];
    const float* W_rkv     = (const float*)d_in[1];
    const float* b_rkv     = (const float*)d_in[2];
    const float* W_o       = (const float*)d_in[3];
    const float* b_o       = (const float*)d_in[4];
    const float* nu_log    = (const float*)d_in[5];
    const float* gamma_log = (const float*)d_in[6];
    float* out = (float*)d_out;

    float *p_rkv = nullptr, *p_x = nullptr;
    __nv_bfloat16 *p_Ah = nullptr, *p_Xh = nullptr, *p_B1 = nullptr, *p_B2 = nullptr;
    cudaGetSymbolAddress((void**)&p_rkv, g_rkv);
    cudaGetSymbolAddress((void**)&p_x, g_x);
    cudaGetSymbolAddress((void**)&p_Ah, g_Ah);
    cudaGetSymbolAddress((void**)&p_Xh, g_Xh);
    cudaGetSymbolAddress((void**)&p_B1, g_B1);
    cudaGetSymbolAddress((void**)&p_B2, g_B2);

    // Operand conversion (hi/lo bf16 split; B transposed to K-major [N, 2K])
    split_rows<<<(MROWS * 256 + 255) / 256, 256>>>(inputs, p_Ah, MROWS * 256);
    split_T<<<dim3(U3 / 32, HD / 32), dim3(32, 8)>>>(W_rkv, p_B1, HD, U3);
    split_T<<<dim3(HD / 32, UD / 32), dim3(32, 8)>>>(W_o, p_B2, UD, HD);

    // GEMM1: rkv = inputs @ W_rkv + b_rkv   [16384, 3072]
    gemm_mma<<<dim3(U3 / 128, MROWS / 128), 256>>>(p_Ah, p_B1, b_rkv, p_rkv, U3);

    // Scan
    scan_phaseA<<<dim3(UD / 256, NCHUNK, BB), 256>>>(nu_log);
    scan_phaseB<<<dim3(UD / 256, BB), 256>>>(nu_log);
    scan_phaseC<<<dim3(UD / 256, NCHUNK, BB), 256>>>(nu_log, gamma_log);

    // GEMM2: out = x @ W_o + b_o   [16384, 1024]
    split_rows<<<(MROWS * 256 + 255) / 256, 256>>>(p_x, p_Xh, MROWS * 256);
    gemm_mma<<<dim3(HD / 128, MROWS / 128), 256>>>(p_Xh, p_B2, b_o, out, HD);
}

// round 5
// speedup vs baseline: 2.1288x; 1.1698x over previous
#include <cuda_runtime.h>
#include <cuda_bf16.h>
#include <math.h>
#include <stdint.h>

// Problem constants
#define BB   4
#define LSEQ 4096
#define HD   1024
#define UD   1024
#define U3   3072
#define NCHUNK 64
#define LC     64
#define K2   2048           // stored split K: [hi | lo]
#define MROWS (BB*LSEQ)     // 16384

// Scratch (allocation-free: __device__ globals)
__device__ float g_rkv[(size_t)BB * LSEQ * U3];        // 192 MB fp32
__device__ float g_x[(size_t)BB * LSEQ * UD];          // 64 MB
__device__ float g_part[(size_t)BB * NCHUNK * 2 * UD]; // 2 MB
__device__ __nv_bfloat16 g_Ah[(size_t)MROWS * K2];     // 64 MB: split(inputs)
__device__ __nv_bfloat16 g_Xh[(size_t)MROWS * K2];     // 64 MB: split(x)
__device__ __nv_bfloat16 g_B1[(size_t)U3 * K2];        // 12 MB: split+T(W_rkv)
__device__ __nv_bfloat16 g_B2[(size_t)HD * K2];        //  4 MB: split+T(W_o)

__device__ __forceinline__ void cpa16(void* s, const void* g) {
    uint32_t sa = (uint32_t)__cvta_generic_to_shared(s);
    asm volatile("cp.async.cg.shared.global [%0], [%1], 16;" :: "r"(sa), "l"(g));
}

// ---------------------------------------------------------------------------
// bf16 warp-MMA GEMM (mma.sync m16n8k16, fp32 accum), 3-term hi/lo split:
//   C = A_hi*B_hi + A_hi*B_lo + A_lo*B_hi   (~fp32 accuracy)
// 96 virtual K-chunks of 32. CTA tile 128x128, 8 warps (2x4).
// 3-stage cp.async pipeline (1 barrier/chunk), ldmatrix fragment loads.
// SMEM rows padded to 40 bf16 (80B): 16B-aligned, conflict-free ldmatrix.
// ---------------------------------------------------------------------------
#define RS   40                 // row stride (bf16 elems)
#define TEL  (128 * RS)         // elems per tile (A or B)
#define SEL  (2 * TEL)          // elems per stage (A + B)
#define STB  (SEL * 2)          // bytes per stage
#define SMEM_GEMM (3 * STB)     // 61440 bytes

__global__ void __launch_bounds__(256, 2) gemm_mma(
    const __nv_bfloat16* __restrict__ A,
    const __nv_bfloat16* __restrict__ Bt,
    const float* __restrict__ bias,
    float* __restrict__ C, int N)
{
    extern __shared__ __nv_bfloat16 smbuf[];
    const uint32_t smem0 = (uint32_t)__cvta_generic_to_shared(smbuf);

    const int tid  = threadIdx.x;
    const int m0   = blockIdx.y * 128;
    const int n0   = blockIdx.x * 128;
    const int warp = tid >> 5;
    const int lane = tid & 31;
    const int wm   = (warp >> 2) * 64;   // 0 or 64
    const int wn   = (warp & 3) * 32;    // 0,32,64,96
    const int gm   = lane >> 2;          // 0..7
    const int kq   = (lane & 3) * 2;     // 0,2,4,6

    // ldmatrix per-lane base offsets (bytes, within a stage)
    const uint32_t aOff = (uint32_t)(((wm + (lane & 7) + ((lane >> 3) & 1) * 8) * RS
                                      + (lane >> 4) * 8) * 2);
    const int l2 = lane & 15;
    const uint32_t bOff = (uint32_t)(TEL * 2 + ((wn + (l2 & 7)) * RS + (l2 >> 3) * 8) * 2);

    float acc[4][4][4];
    #pragma unroll
    for (int i = 0; i < 4; i++)
        #pragma unroll
        for (int j = 0; j < 4; j++)
            #pragma unroll
            for (int t = 0; t < 4; t++)
                acc[i][j][t] = 0.f;

    // loader: virtual chunk ci (0..95) -> stage st
    const int lr = tid >> 2;        // 0..63 base row
    const int lj = (tid & 3) * 8;   // 16B segment within 64B row-chunk
    auto load_chunk = [&](int ci, int st) {
        const int s   = ci >> 5;            // segment 0,1,2
        const int kof = (ci & 31) << 5;     // 0..992
        const size_t kA = (size_t)((s == 2) ? 1024 : 0) + kof;   // A: hi,hi,lo
        const size_t kB = (size_t)((s == 1) ? 1024 : 0) + kof;   // B: hi,lo,hi
        __nv_bfloat16* As = smbuf + (size_t)st * SEL;
        __nv_bfloat16* Bs = As + TEL;
        #pragma unroll
        for (int h = 0; h < 2; h++) {
            int r = lr + h * 64;
            cpa16(As + r * RS + lj, A  + (size_t)(m0 + r) * K2 + kA + lj);
            cpa16(Bs + r * RS + lj, Bt + (size_t)(n0 + r) * K2 + kB + lj);
        }
        asm volatile("cp.async.commit_group;");
    };

    load_chunk(0, 0);
    load_chunk(1, 1);

    const int NCH = 96;
    for (int ci = 0; ci < NCH; ci++) {
        const int st = ci % 3;
        if (ci < NCH - 1) {
            asm volatile("cp.async.wait_group 1;" ::: "memory");
        } else {
            asm volatile("cp.async.wait_group 0;" ::: "memory");
        }
        __syncthreads();
        if (ci + 2 < NCH) load_chunk(ci + 2, (ci + 2) % 3);

        const uint32_t aBase = smem0 + (uint32_t)st * STB + aOff;
        const uint32_t bBase = smem0 + (uint32_t)st * STB + bOff;

        #pragma unroll
        for (int kk = 0; kk < 2; kk++) {
            uint32_t af[4][4], bf[4][2];
            #pragma unroll
            for (int i = 0; i < 4; i++)
                asm volatile(
                    "ldmatrix.sync.aligned.m8n8.x4.shared.b16 {%0,%1,%2,%3}, [%4];"
                    : "=r"(af[i][0]), "=r"(af[i][1]), "=r"(af[i][2]), "=r"(af[i][3])
                    : "r"(aBase + (uint32_t)(i * 16 * RS * 2 + kk * 32)));
            #pragma unroll
            for (int j = 0; j < 4; j++)
                asm volatile(
                    "ldmatrix.sync.aligned.m8n8.x2.shared.b16 {%0,%1}, [%2];"
                    : "=r"(bf[j][0]), "=r"(bf[j][1])
                    : "r"(bBase + (uint32_t)(j * 8 * RS * 2 + kk * 32)));
            #pragma unroll
            for (int i = 0; i < 4; i++)
                #pragma unroll
                for (int j = 0; j < 4; j++)
                    asm volatile(
                        "mma.sync.aligned.m16n8k16.row.col.f32.bf16.bf16.f32 "
                        "{%0,%1,%2,%3}, {%4,%5,%6,%7}, {%8,%9}, {%0,%1,%2,%3};"
                        : "+f"(acc[i][j][0]), "+f"(acc[i][j][1]),
                          "+f"(acc[i][j][2]), "+f"(acc[i][j][3])
                        : "r"(af[i][0]), "r"(af[i][1]), "r"(af[i][2]), "r"(af[i][3]),
                          "r"(bf[j][0]), "r"(bf[j][1]));
        }
    }

    // Epilogue: bias + store (float2 per fragment row)
    #pragma unroll
    for (int j = 0; j < 4; j++) {
        const int col = n0 + wn + j * 8 + kq;
        const float b0 = bias[col], b1 = bias[col + 1];
        #pragma unroll
        for (int i = 0; i < 4; i++) {
            const int row = m0 + wm + i * 16 + gm;
            float2 v0 = make_float2(acc[i][j][0] + b0, acc[i][j][1] + b1);
            float2 v1 = make_float2(acc[i][j][2] + b0, acc[i][j][3] + b1);
            *(float2*)&C[(size_t)row * N + col]       = v0;
            *(float2*)&C[(size_t)(row + 8) * N + col] = v1;
        }
    }
}

// ---------------------------------------------------------------------------
// fp32 -> bf16 hi/lo split, row layout [R,1024] -> [R,2048] ([hi|lo])
// ---------------------------------------------------------------------------
__global__ void __launch_bounds__(256) split_rows(const float* __restrict__ X,
                                                  __nv_bfloat16* __restrict__ Y, int total4)
{
    int idx = blockIdx.x * 256 + threadIdx.x;
    if (idx >= total4) return;
    int r = idx >> 8;          // 256 float4 per row (K=1024)
    int c4 = idx & 255;
    float4 v = ((const float4*)X)[idx];
    float f[4] = { v.x, v.y, v.z, v.w };
    ushort4 hv, lv;
    unsigned short* hp = &hv.x; unsigned short* lp = &lv.x;
    #pragma unroll
    for (int i = 0; i < 4; i++) {
        __nv_bfloat16 h = __float2bfloat16(f[i]);
        __nv_bfloat16 l = __float2bfloat16(f[i] - __bfloat162float(h));
        hp[i] = __bfloat16_as_ushort(h);
        lp[i] = __bfloat16_as_ushort(l);
    }
    size_t o = (size_t)r * K2 + (c4 << 2);
    *(ushort4*)((unsigned short*)Y + o)         = hv;
    *(ushort4*)((unsigned short*)Y + o + 1024)  = lv;
}

// ---------------------------------------------------------------------------
// W[K,N] fp32 -> Bt[N,2048] bf16 (transpose + split), tiled 32x32
// ---------------------------------------------------------------------------
__global__ void split_T(const float* __restrict__ W, __nv_bfloat16* __restrict__ Bt,
                        int Kdim, int Ncols)
{
    __shared__ float t[32][33];
    int n = blockIdx.x * 32 + threadIdx.x;
    int k0 = blockIdx.y * 32;
    for (int i = threadIdx.y; i < 32; i += 8)
        t[i][threadIdx.x] = W[(size_t)(k0 + i) * Ncols + n];
    __syncthreads();
    int k = k0 + threadIdx.x;
    for (int i = threadIdx.y; i < 32; i += 8) {
        int nn = blockIdx.x * 32 + i;
        float v = t[threadIdx.x][i];
        __nv_bfloat16 h = __float2bfloat16(v);
        __nv_bfloat16 l = __float2bfloat16(v - __bfloat162float(h));
        Bt[(size_t)nn * K2 + k]        = h;
        Bt[(size_t)nn * K2 + 1024 + k] = l;
    }
}

// ---------------------------------------------------------------------------
// Chunked linear-recurrence scan (3 phases)
// ---------------------------------------------------------------------------
__global__ void __launch_bounds__(256) scan_phaseA(const float* __restrict__ nu_log)
{
    const int c = blockIdx.x * blockDim.x + threadIdx.x;
    const int chunk = blockIdx.y;
    const int b = blockIdx.z;
    const float lam = expf(-expf(nu_log[c]));

    size_t base = ((size_t)b * LSEQ + (size_t)chunk * LC) * U3;
    float y1 = 0.f, y2 = 0.f;
    #pragma unroll 4
    for (int i = 0; i < LC; i++) {
        size_t off = base + (size_t)i * U3;
        float kr = g_rkv[off + UD + c];
        float vr = g_rkv[off + 2 * UD + c];
        float kk = expf(kr);
        float kv = kk * vr;
        g_rkv[off + UD + c]     = kk;
        g_rkv[off + 2 * UD + c] = kv;
        y1 = fmaf(y1, lam, kv);
        y2 = fmaf(y2, lam, kk);
    }
    size_t p = (size_t)(b * NCHUNK + chunk) * 2 * UD + c;
    g_part[p]      = y1;
    g_part[p + UD] = y2;
}

__global__ void __launch_bounds__(256) scan_phaseB(const float* __restrict__ nu_log)
{
    const int c = blockIdx.x * blockDim.x + threadIdx.x;
    const int b = blockIdx.y;
    const float lam = expf(-expf(nu_log[c]));
    const float lamLc = powf(lam, (float)LC);
    float Y1 = 0.f, Y2 = 0.f;
    for (int j = 0; j < NCHUNK; j++) {
        size_t p = (size_t)(b * NCHUNK + j) * 2 * UD + c;
        float S1 = g_part[p], S2 = g_part[p + UD];
        g_part[p]      = Y1;
        g_part[p + UD] = Y2;
        Y1 = fmaf(Y1, lamLc, S1);
        Y2 = fmaf(Y2, lamLc, S2);
    }
}

__global__ void __launch_bounds__(256) scan_phaseC(const float* __restrict__ nu_log,
                                                   const float* __restrict__ gamma_log)
{
    const int c = blockIdx.x * blockDim.x + threadIdx.x;
    const int chunk = blockIdx.y;
    const int b = blockIdx.z;
    const float lam = expf(-expf(nu_log[c]));
    const float gamma = expf(nu_log[c] + gamma_log[c]) - 1.f;

    size_t p = (size_t)(b * NCHUNK + chunk) * 2 * UD + c;
    float y1 = g_part[p];
    float y2 = g_part[p + UD];

    size_t base  = ((size_t)b * LSEQ + (size_t)chunk * LC) * U3;
    size_t xbase = ((size_t)b * LSEQ + (size_t)chunk * LC) * UD;
    #pragma unroll 4
    for (int i = 0; i < LC; i++) {
        size_t off = base + (size_t)i * U3;
        float rr = g_rkv[off + c];
        float kk = g_rkv[off + UD + c];
        float kv = g_rkv[off + 2 * UD + c];
        y1 = fmaf(y1, lam, kv);
        y2 = fmaf(y2, lam, kk);
        float r = 1.f / (1.f + expf(-rr));
        float x = (y1 + gamma * kv) / (y2 + gamma * kk + 1e-6f) * r;
        g_x[xbase + (size_t)i * UD + c] = x;
    }
}

// ---------------------------------------------------------------------------
// Launch
// ---------------------------------------------------------------------------
extern "C" void kernel_launch(void* const* d_in, const int* in_sizes, int n_in,
                              void* d_out, int out_size)
{
    const float* inputs    = (const float*)d_in[0];
    const float* W_rkv     = (const float*)d_in[1];
    const float* b_rkv     = (const float*)d_in[2];
    const float* W_o       = (const float*)d_in[3];
    const float* b_o       = (const float*)d_in[4];
    const float* nu_log    = (const float*)d_in[5];
    const float* gamma_log = (const float*)d_in[6];
    float* out = (float*)d_out;

    float *p_rkv = nullptr, *p_x = nullptr;
    __nv_bfloat16 *p_Ah = nullptr, *p_Xh = nullptr, *p_B1 = nullptr, *p_B2 = nullptr;
    cudaGetSymbolAddress((void**)&p_rkv, g_rkv);
    cudaGetSymbolAddress((void**)&p_x, g_x);
    cudaGetSymbolAddress((void**)&p_Ah, g_Ah);
    cudaGetSymbolAddress((void**)&p_Xh, g_Xh);
    cudaGetSymbolAddress((void**)&p_B1, g_B1);
    cudaGetSymbolAddress((void**)&p_B2, g_B2);

    static bool attr_set = false;
    if (!attr_set) {
        cudaFuncSetAttribute(gemm_mma, cudaFuncAttributeMaxDynamicSharedMemorySize, SMEM_GEMM);
        attr_set = true;
    }

    // Operand conversion (hi/lo bf16 split; B transposed to K-major [N, 2K])
    split_rows<<<(MROWS * 256 + 255) / 256, 256>>>(inputs, p_Ah, MROWS * 256);
    split_T<<<dim3(U3 / 32, HD / 32), dim3(32, 8)>>>(W_rkv, p_B1, HD, U3);
    split_T<<<dim3(HD / 32, UD / 32), dim3(32, 8)>>>(W_o, p_B2, UD, HD);

    // GEMM1: rkv = inputs @ W_rkv + b_rkv   [16384, 3072]
    gemm_mma<<<dim3(U3 / 128, MROWS / 128), 256, SMEM_GEMM>>>(p_Ah, p_B1, b_rkv, p_rkv, U3);

    // Scan
    scan_phaseA<<<dim3(UD / 256, NCHUNK, BB), 256>>>(nu_log);
    scan_phaseB<<<dim3(UD / 256, BB), 256>>>(nu_log);
    scan_phaseC<<<dim3(UD / 256, NCHUNK, BB), 256>>>(nu_log, gamma_log);

    // GEMM2: out = x @ W_o + b_o   [16384, 1024]
    split_rows<<<(MROWS * 256 + 255) / 256, 256>>>(p_x, p_Xh, MROWS * 256);
    gemm_mma<<<dim3(HD / 128, MROWS / 128), 256, SMEM_GEMM>>>(p_Xh, p_B2, b_o, out, HD);
}